// round 1
// baseline (speedup 1.0000x reference)
#include <cuda_runtime.h>
#include <math.h>

#define SEQ 2048
#define DM  1024
#define DFF 4096
#define NH  16
#define DKH 64

// ---------------- scratch (no runtime allocation allowed) ----------------
__device__ float g_normx[SEQ * DM];
__device__ float g_h[SEQ * DM];
__device__ float g_q[SEQ * DM];
__device__ float g_k[SEQ * DM];
__device__ float g_v[SEQ * DM];
__device__ float g_ctx[SEQ * DM];
__device__ float g_mha[SEQ * DM];
__device__ float g_part1[SEQ * DM];
__device__ float g_norm2[SEQ * DM];
__device__ float g_ff1[SEQ * DFF];

// ---------------- LayerNorm: y = g*((x-mean)/(std+eps)) + b ----------------
__global__ void ln_kernel(const float* __restrict__ x,
                          const float* __restrict__ gamma,
                          const float* __restrict__ beta,
                          float* __restrict__ out) {
    int row = blockIdx.x;
    const float* xr = x + (size_t)row * DM;
    __shared__ float red[256];
    int t = threadIdx.x;

    float s = 0.f;
    for (int i = t; i < DM; i += 256) s += xr[i];
    red[t] = s; __syncthreads();
    for (int off = 128; off > 0; off >>= 1) {
        if (t < off) red[t] += red[t + off];
        __syncthreads();
    }
    float mean = red[0] * (1.0f / DM);
    __syncthreads();

    float v = 0.f;
    for (int i = t; i < DM; i += 256) { float d = xr[i] - mean; v += d * d; }
    red[t] = v; __syncthreads();
    for (int off = 128; off > 0; off >>= 1) {
        if (t < off) red[t] += red[t + off];
        __syncthreads();
    }
    float rstd = 1.0f / (sqrtf(red[0] * (1.0f / DM)) + 1e-6f);

    float* o = out + (size_t)row * DM;
    for (int i = t; i < DM; i += 256)
        o[i] = gamma[i] * ((xr[i] - mean) * rstd) + beta[i];
}

// ---------------- causal softmax over attn rows; zero masked tail ----------------
__global__ void softmax_causal_kernel(float* __restrict__ attn) {
    int row = blockIdx.x;        // query index 0..SEQ-1
    int hh  = blockIdx.y;        // head
    float* p = attn + ((size_t)hh * SEQ + row) * SEQ;
    int L = row + 1;
    int t = threadIdx.x;
    __shared__ float red[256];

    float m = -1e30f;
    for (int i = t; i < L; i += 256) m = fmaxf(m, p[i]);
    red[t] = m; __syncthreads();
    for (int off = 128; off > 0; off >>= 1) {
        if (t < off) red[t] = fmaxf(red[t], red[t + off]);
        __syncthreads();
    }
    m = red[0]; __syncthreads();

    float sum = 0.f;
    for (int i = t; i < L; i += 256) { float e = expf(p[i] - m); p[i] = e; sum += e; }
    red[t] = sum; __syncthreads();
    for (int off = 128; off > 0; off >>= 1) {
        if (t < off) red[t] += red[t + off];
        __syncthreads();
    }
    float inv = 1.0f / red[0];
    for (int i = t; i < L; i += 256) p[i] *= inv;
    for (int i = L + t; i < SEQ; i += 256) p[i] = 0.f;
}

// ---------------- generic batched SGEMM ----------------
// C[z] = alpha * A[z] (@ or @T) B[z] + bias + (res) with optional relu.
// NN: C[m,n] = sum_k A[m,k]*B[k,n]     NT: C[m,n] = sum_k A[m,k]*B[n,k]
// 128x128 tile, K-step 8, 256 threads, 8x8 per-thread.
template <bool NT, bool RELU>
__global__ void __launch_bounds__(256)
sgemm_kernel(const float* __restrict__ A, const float* __restrict__ B,
             const float* __restrict__ bias, const float* __restrict__ res,
             float* __restrict__ C,
             int M, int N, int K, int lda, int ldb, int ldc,
             long long aZ, long long bZ, long long cZ, float alpha) {
    __shared__ float As[8][128];
    __shared__ float Bs[8][128];

    A += (size_t)blockIdx.z * aZ;
    B += (size_t)blockIdx.z * bZ;
    C += (size_t)blockIdx.z * cZ;

    const int tid = threadIdx.x;
    const int m0 = blockIdx.y * 128;
    const int n0 = blockIdx.x * 128;

    const int arow = tid >> 1;           // 0..127
    const int acol = (tid & 1) * 4;      // 0 or 4
    const int tr = (tid >> 4) * 8;       // 0..120 (row offset)
    const int tc = (tid & 15) * 8;       // 0..120 (col offset)

    float acc[8][8];
#pragma unroll
    for (int i = 0; i < 8; i++)
#pragma unroll
        for (int j = 0; j < 8; j++) acc[i][j] = 0.f;

    for (int k0 = 0; k0 < K; k0 += 8) {
        // --- load A tile (128x8), store transposed ---
        {
            float4 a4 = make_float4(0.f, 0.f, 0.f, 0.f);
            int gr = m0 + arow;
            if (gr < M)
                a4 = *(const float4*)(A + (size_t)gr * lda + k0 + acol);
            As[acol + 0][arow] = a4.x;
            As[acol + 1][arow] = a4.y;
            As[acol + 2][arow] = a4.z;
            As[acol + 3][arow] = a4.w;
        }
        // --- load B tile ---
        if (NT) {
            // B is [N,K]: rows=n, cols=k -> transpose into Bs[k][n]
            float4 b4 = make_float4(0.f, 0.f, 0.f, 0.f);
            int gr = n0 + arow;
            if (gr < N)
                b4 = *(const float4*)(B + (size_t)gr * ldb + k0 + acol);
            Bs[acol + 0][arow] = b4.x;
            Bs[acol + 1][arow] = b4.y;
            Bs[acol + 2][arow] = b4.z;
            Bs[acol + 3][arow] = b4.w;
        } else {
            // B is [K,N]
            int brow = tid >> 5;              // 0..7
            int bcol = (tid & 31) * 4;        // 0..124
            float4 b4 = make_float4(0.f, 0.f, 0.f, 0.f);
            if (n0 + bcol < N)
                b4 = *(const float4*)(B + (size_t)(k0 + brow) * ldb + n0 + bcol);
            *(float4*)&Bs[brow][bcol] = b4;
        }
        __syncthreads();

#pragma unroll
        for (int kk = 0; kk < 8; kk++) {
            float4 a0 = *(const float4*)&As[kk][tr];
            float4 a1 = *(const float4*)&As[kk][tr + 4];
            float4 b0 = *(const float4*)&Bs[kk][tc];
            float4 b1 = *(const float4*)&Bs[kk][tc + 4];
            float a[8] = {a0.x, a0.y, a0.z, a0.w, a1.x, a1.y, a1.z, a1.w};
            float b[8] = {b0.x, b0.y, b0.z, b0.w, b1.x, b1.y, b1.z, b1.w};
#pragma unroll
            for (int i = 0; i < 8; i++)
#pragma unroll
                for (int j = 0; j < 8; j++)
                    acc[i][j] += a[i] * b[j];
        }
        __syncthreads();
    }

    // --- epilogue ---
#pragma unroll
    for (int i = 0; i < 8; i++) {
        int r = m0 + tr + i;
        if (r >= M) continue;
#pragma unroll
        for (int j = 0; j < 8; j++) {
            int c = n0 + tc + j;
            if (c >= N) continue;
            float v = acc[i][j] * alpha;
            if (bias) v += bias[c];
            if (RELU) v = fmaxf(v, 0.f);
            if (res) v += res[(size_t)r * ldc + c];
            C[(size_t)r * ldc + c] = v;
        }
    }
}

// ---------------- launch ----------------
extern "C" void kernel_launch(void* const* d_in, const int* in_sizes, int n_in,
                              void* d_out, int out_size) {
    (void)in_sizes; (void)n_in; (void)out_size;

    const float* x     = (const float*)d_in[0];
    const float* g1    = (const float*)d_in[1];
    const float* beta1 = (const float*)d_in[2];
    const float* W_in  = (const float*)d_in[3];
    const float* b_in  = (const float*)d_in[4];
    const float* Wq    = (const float*)d_in[5];
    const float* bq    = (const float*)d_in[6];
    const float* Wk    = (const float*)d_in[7];
    const float* bk    = (const float*)d_in[8];
    const float* Wv    = (const float*)d_in[9];
    const float* bv    = (const float*)d_in[10];
    const float* Wo    = (const float*)d_in[11];
    const float* bo    = (const float*)d_in[12];
    const float* W2    = (const float*)d_in[13];
    const float* b2    = (const float*)d_in[14];
    const float* g2    = (const float*)d_in[15];
    const float* beta2 = (const float*)d_in[16];
    const float* Wf1   = (const float*)d_in[17];
    const float* bf1   = (const float*)d_in[18];
    const float* Wf2   = (const float*)d_in[19];
    const float* bf2   = (const float*)d_in[20];

    float* out  = (float*)d_out;
    float* attn = out + (size_t)SEQ * DM;   // [NH, SEQ, SEQ]

    float *normx, *h, *q, *k, *v, *ctx, *mha, *part1, *norm2, *ff1;
    cudaGetSymbolAddress((void**)&normx, g_normx);
    cudaGetSymbolAddress((void**)&h,     g_h);
    cudaGetSymbolAddress((void**)&q,     g_q);
    cudaGetSymbolAddress((void**)&k,     g_k);
    cudaGetSymbolAddress((void**)&v,     g_v);
    cudaGetSymbolAddress((void**)&ctx,   g_ctx);
    cudaGetSymbolAddress((void**)&mha,   g_mha);
    cudaGetSymbolAddress((void**)&part1, g_part1);
    cudaGetSymbolAddress((void**)&norm2, g_norm2);
    cudaGetSymbolAddress((void**)&ff1,   g_ff1);

    const long long SS = (long long)SEQ * SEQ;

    // 1. LN1
    ln_kernel<<<SEQ, 256>>>(x, g1, beta1, normx);

    // 2. h = norm_x @ W_in + b_in
    sgemm_kernel<false, false><<<dim3(DM / 128, SEQ / 128, 1), 256>>>(
        normx, W_in, b_in, nullptr, h, SEQ, DM, DM, DM, DM, DM, 0, 0, 0, 1.f);

    // 3. q/k/v projections
    sgemm_kernel<false, false><<<dim3(DM / 128, SEQ / 128, 1), 256>>>(
        h, Wq, bq, nullptr, q, SEQ, DM, DM, DM, DM, DM, 0, 0, 0, 1.f);
    sgemm_kernel<false, false><<<dim3(DM / 128, SEQ / 128, 1), 256>>>(
        h, Wk, bk, nullptr, k, SEQ, DM, DM, DM, DM, DM, 0, 0, 0, 1.f);
    sgemm_kernel<false, false><<<dim3(DM / 128, SEQ / 128, 1), 256>>>(
        h, Wv, bv, nullptr, v, SEQ, DM, DM, DM, DM, DM, 0, 0, 0, 1.f);

    // 4. scores = q @ k^T / 8 (per head, batched over z)
    sgemm_kernel<true, false><<<dim3(SEQ / 128, SEQ / 128, NH), 256>>>(
        q, k, nullptr, nullptr, attn, SEQ, SEQ, DKH, DM, DM, SEQ,
        DKH, DKH, SS, 0.125f);

    // 5. causal softmax (writes zeros in masked region)
    softmax_causal_kernel<<<dim3(SEQ, NH), 256>>>(attn);

    // 6. ctx = attn @ v (per head)
    sgemm_kernel<false, false><<<dim3(1, SEQ / 128, NH), 256>>>(
        attn, v, nullptr, nullptr, ctx, SEQ, DKH, SEQ, SEQ, DM, DM,
        SS, DKH, DKH, 1.f);

    // 7. mha = ctx @ Wo + bo
    sgemm_kernel<false, false><<<dim3(DM / 128, SEQ / 128, 1), 256>>>(
        ctx, Wo, bo, nullptr, mha, SEQ, DM, DM, DM, DM, DM, 0, 0, 0, 1.f);

    // 8. part1 = x + mha @ W2 + b2
    sgemm_kernel<false, false><<<dim3(DM / 128, SEQ / 128, 1), 256>>>(
        mha, W2, b2, x, part1, SEQ, DM, DM, DM, DM, DM, 0, 0, 0, 1.f);

    // 9. LN2
    ln_kernel<<<SEQ, 256>>>(part1, g2, beta2, norm2);

    // 10. ff1 = relu(norm2 @ Wf1 + bf1)
    sgemm_kernel<false, true><<<dim3(DFF / 128, SEQ / 128, 1), 256>>>(
        norm2, Wf1, bf1, nullptr, ff1, SEQ, DFF, DM, DM, DFF, DFF, 0, 0, 0, 1.f);

    // 11. out = norm2 + ff1 @ Wf2 + bf2
    sgemm_kernel<false, false><<<dim3(DM / 128, SEQ / 128, 1), 256>>>(
        ff1, Wf2, bf2, norm2, out, SEQ, DM, DFF, DFF, DM, DM, 0, 0, 0, 1.f);
}

// round 4
// speedup vs baseline: 1.6074x; 1.6074x over previous
#include <cuda_runtime.h>
#include <math.h>
#include <stdint.h>

#define SEQ 2048
#define DM  1024
#define DFF 4096
#define NH  16
#define DKH 64

// ---------------- scratch (no runtime allocation allowed) ----------------
__device__ float g_normx[SEQ * DM];
__device__ float g_h[SEQ * DM];
__device__ float g_qkv[SEQ * 3 * DM];
__device__ float g_wqkv[DM * 3 * DM];
__device__ float g_bqkv[3 * DM];
__device__ float g_ctx[SEQ * DM];
__device__ float g_mha[SEQ * DM];
__device__ float g_part1[SEQ * DM];
__device__ float g_norm2[SEQ * DM];
__device__ float g_ff1[SEQ * DFF];

// ---------------- helpers ----------------
__device__ __forceinline__ uint32_t f2tf32(float f) {
    uint32_t u;
    asm("cvt.rna.tf32.f32 %0, %1;" : "=r"(u) : "f"(f));
    return u;
}

__device__ __forceinline__ void mma_tf32(float* d, const uint32_t* a, const uint32_t* b) {
    asm volatile(
        "mma.sync.aligned.m16n8k8.row.col.f32.tf32.tf32.f32 "
        "{%0,%1,%2,%3}, {%4,%5,%6,%7}, {%8,%9}, {%0,%1,%2,%3};\n"
        : "+f"(d[0]), "+f"(d[1]), "+f"(d[2]), "+f"(d[3])
        : "r"(a[0]), "r"(a[1]), "r"(a[2]), "r"(a[3]), "r"(b[0]), "r"(b[1]));
}

// ---------------- pack W_qkv / b_qkv (replaces memcpy2D nodes) ----------------
__global__ void pack_qkv_kernel(const float* __restrict__ Wq,
                                const float* __restrict__ Wk,
                                const float* __restrict__ Wv,
                                const float* __restrict__ bq,
                                const float* __restrict__ bk,
                                const float* __restrict__ bv,
                                float* __restrict__ W, float* __restrict__ b) {
    int idx4 = blockIdx.x * 256 + threadIdx.x;      // over DM*DM/4 float4s
    int r  = idx4 / (DM / 4);
    int c4 = idx4 % (DM / 4);
    float4 q4 = *(const float4*)(Wq + (size_t)r * DM + c4 * 4);
    float4 k4 = *(const float4*)(Wk + (size_t)r * DM + c4 * 4);
    float4 v4 = *(const float4*)(Wv + (size_t)r * DM + c4 * 4);
    float* wr = W + (size_t)r * (3 * DM);
    *(float4*)(wr + c4 * 4)          = q4;
    *(float4*)(wr + DM + c4 * 4)     = k4;
    *(float4*)(wr + 2 * DM + c4 * 4) = v4;
    if (idx4 < DM) {
        b[idx4]          = bq[idx4];
        b[DM + idx4]     = bk[idx4];
        b[2 * DM + idx4] = bv[idx4];
    }
}

// ---------------- LayerNorm: y = g*((x-mean)/(std+eps)) + b ----------------
__global__ void ln_kernel(const float* __restrict__ x,
                          const float* __restrict__ gamma,
                          const float* __restrict__ beta,
                          float* __restrict__ out) {
    int row = blockIdx.x;
    const float* xr = x + (size_t)row * DM;
    __shared__ float red[256];
    int t = threadIdx.x;

    float s = 0.f;
    for (int i = t; i < DM; i += 256) s += xr[i];
    red[t] = s; __syncthreads();
    for (int off = 128; off > 0; off >>= 1) {
        if (t < off) red[t] += red[t + off];
        __syncthreads();
    }
    float mean = red[0] * (1.0f / DM);
    __syncthreads();

    float v = 0.f;
    for (int i = t; i < DM; i += 256) { float d = xr[i] - mean; v += d * d; }
    red[t] = v; __syncthreads();
    for (int off = 128; off > 0; off >>= 1) {
        if (t < off) red[t] += red[t + off];
        __syncthreads();
    }
    float rstd = 1.0f / (sqrtf(red[0] * (1.0f / DM)) + 1e-6f);

    float* o = out + (size_t)row * DM;
    for (int i = t; i < DM; i += 256)
        o[i] = gamma[i] * ((xr[i] - mean) * rstd) + beta[i];
}

// ---------------- causal softmax; zero masked tail ----------------
__global__ void softmax_causal_kernel(float* __restrict__ attn) {
    int row = blockIdx.x;
    int hh  = blockIdx.y;
    float* p = attn + ((size_t)hh * SEQ + row) * SEQ;
    int L = row + 1;
    int t = threadIdx.x;
    __shared__ float red[256];

    float m = -1e30f;
    for (int i = t; i < L; i += 256) m = fmaxf(m, p[i]);
    red[t] = m; __syncthreads();
    for (int off = 128; off > 0; off >>= 1) {
        if (t < off) red[t] = fmaxf(red[t], red[t + off]);
        __syncthreads();
    }
    m = red[0]; __syncthreads();

    float sum = 0.f;
    for (int i = t; i < L; i += 256) { float e = expf(p[i] - m); p[i] = e; sum += e; }
    red[t] = sum; __syncthreads();
    for (int off = 128; off > 0; off >>= 1) {
        if (t < off) red[t] += red[t + off];
        __syncthreads();
    }
    float inv = 1.0f / red[0];
    for (int i = t; i < L; i += 256) p[i] *= inv;
    for (int i = L + t; i < SEQ; i += 256) p[i] = 0.f;
}

// ---------------- 3xTF32 tensor-core GEMM ----------------
// C[z] = alpha * A[z] (@ or @T) B[z] + bias (+relu) (+res)
// BM x BN CTA tile, BK=16, 256 threads (8 warps), warp tile WM x WN.
// Requires M % BM == 0, N % BN == 0, K % 16 == 0 (all shapes here comply).
template <int BM, int BN, int WM, int WN, bool NT, bool RELU>
__global__ void __launch_bounds__(256, 1)
mma_gemm(const float* __restrict__ A, const float* __restrict__ B,
         const float* __restrict__ bias, const float* __restrict__ res,
         float* __restrict__ C,
         int K, int lda, int ldb, int ldc,
         long long aZ, long long bZ, long long cZ, float alpha) {
    constexpr int BK = 16;
    constexpr int AS = BM + 8;        // padded row stride (words)
    constexpr int BS = BN + 8;
    constexpr int WARPS_N = BN / WN;
    constexpr int MI = WM / 16;
    constexpr int NJ = WN / 8;
    constexpr int NA4 = (BM * BK) / (4 * 256);  // float4 loads per thread (A)
    constexpr int NB4 = (BK * BN) / (4 * 256);  // float4 loads per thread (B)

    __shared__ uint32_t sAhi[BK][AS];
    __shared__ uint32_t sAlo[BK][AS];
    __shared__ uint32_t sBhi[BK][BS];
    __shared__ uint32_t sBlo[BK][BS];

    A += (size_t)blockIdx.z * aZ;
    B += (size_t)blockIdx.z * bZ;
    C += (size_t)blockIdx.z * cZ;

    const int tid  = threadIdx.x;
    const int lane = tid & 31;
    const int wid  = tid >> 5;
    const int g    = lane >> 2;   // group (0..7)
    const int tg   = lane & 3;    // thread in group

    const int m0 = blockIdx.y * BM;
    const int n0 = blockIdx.x * BN;
    const int wm0 = (wid / WARPS_N) * WM;
    const int wn0 = (wid % WARPS_N) * WN;

    float acc[MI][NJ][4];
#pragma unroll
    for (int i = 0; i < MI; i++)
#pragma unroll
        for (int j = 0; j < NJ; j++)
#pragma unroll
            for (int c = 0; c < 4; c++) acc[i][j][c] = 0.f;

    float4 ra[NA4], rb[NB4];

    auto loadA = [&](int k0) {
#pragma unroll
        for (int i = 0; i < NA4; i++) {
            int flat = tid + i * 256;
            int r = flat % BM, cg = flat / BM;
            ra[i] = *(const float4*)(A + (size_t)(m0 + r) * lda + k0 + cg * 4);
        }
    };
    auto loadB = [&](int k0) {
#pragma unroll
        for (int i = 0; i < NB4; i++) {
            int flat = tid + i * 256;
            if (NT) {
                int r = flat % BN, cg = flat / BN;  // r = n row, cg = k group
                rb[i] = *(const float4*)(B + (size_t)(n0 + r) * ldb + k0 + cg * 4);
            } else {
                int c4 = flat % (BN / 4), r = flat / (BN / 4);
                rb[i] = *(const float4*)(B + (size_t)(k0 + r) * ldb + n0 + c4 * 4);
            }
        }
    };
    auto storeA = [&]() {
#pragma unroll
        for (int i = 0; i < NA4; i++) {
            int flat = tid + i * 256;
            int r = flat % BM, cg = flat / BM;
            float f[4] = {ra[i].x, ra[i].y, ra[i].z, ra[i].w};
#pragma unroll
            for (int j = 0; j < 4; j++) {
                uint32_t hi = f2tf32(f[j]);
                uint32_t lo = f2tf32(f[j] - __uint_as_float(hi));
                sAhi[cg * 4 + j][r] = hi;
                sAlo[cg * 4 + j][r] = lo;
            }
        }
    };
    auto storeB = [&]() {
#pragma unroll
        for (int i = 0; i < NB4; i++) {
            int flat = tid + i * 256;
            float f[4] = {rb[i].x, rb[i].y, rb[i].z, rb[i].w};
            if (NT) {
                int r = flat % BN, cg = flat / BN;
#pragma unroll
                for (int j = 0; j < 4; j++) {
                    uint32_t hi = f2tf32(f[j]);
                    uint32_t lo = f2tf32(f[j] - __uint_as_float(hi));
                    sBhi[cg * 4 + j][r] = hi;
                    sBlo[cg * 4 + j][r] = lo;
                }
            } else {
                int c4 = flat % (BN / 4), r = flat / (BN / 4);
                uint4 hi4, lo4;
                uint32_t* hp = (uint32_t*)&hi4;
                uint32_t* lp = (uint32_t*)&lo4;
#pragma unroll
                for (int j = 0; j < 4; j++) {
                    hp[j] = f2tf32(f[j]);
                    lp[j] = f2tf32(f[j] - __uint_as_float(hp[j]));
                }
                *(uint4*)&sBhi[r][c4 * 4] = hi4;
                *(uint4*)&sBlo[r][c4 * 4] = lo4;
            }
        }
    };

    // prologue
    loadA(0); loadB(0);
    storeA(); storeB();
    __syncthreads();

    for (int k0 = BK; k0 <= K; k0 += BK) {
        bool more = (k0 < K);
        if (more) { loadA(k0); loadB(k0); }

        // compute current smem tile
#pragma unroll
        for (int kk = 0; kk < BK; kk += 8) {
            uint32_t ah[MI][4], al[MI][4], bh[NJ][2], bl[NJ][2];
#pragma unroll
            for (int mi = 0; mi < MI; mi++) {
                const int r = wm0 + mi * 16 + g;
                const uint32_t* h0 = &sAhi[kk + tg][0];
                const uint32_t* h4 = &sAhi[kk + tg + 4][0];
                const uint32_t* l0 = &sAlo[kk + tg][0];
                const uint32_t* l4 = &sAlo[kk + tg + 4][0];
                ah[mi][0] = h0[r];  ah[mi][1] = h0[r + 8];
                ah[mi][2] = h4[r];  ah[mi][3] = h4[r + 8];
                al[mi][0] = l0[r];  al[mi][1] = l0[r + 8];
                al[mi][2] = l4[r];  al[mi][3] = l4[r + 8];
            }
#pragma unroll
            for (int nj = 0; nj < NJ; nj++) {
                const int c = wn0 + nj * 8 + g;
                bh[nj][0] = sBhi[kk + tg][c];
                bh[nj][1] = sBhi[kk + tg + 4][c];
                bl[nj][0] = sBlo[kk + tg][c];
                bl[nj][1] = sBlo[kk + tg + 4][c];
            }
#pragma unroll
            for (int mi = 0; mi < MI; mi++)
#pragma unroll
                for (int nj = 0; nj < NJ; nj++) {
                    mma_tf32(acc[mi][nj], al[mi], bh[nj]);
                    mma_tf32(acc[mi][nj], ah[mi], bl[nj]);
                    mma_tf32(acc[mi][nj], ah[mi], bh[nj]);
                }
        }
        __syncthreads();
        if (more) {
            storeA(); storeB();
            __syncthreads();
        }
    }

    // epilogue
#pragma unroll
    for (int mi = 0; mi < MI; mi++) {
#pragma unroll
        for (int nj = 0; nj < NJ; nj++) {
            int r = m0 + wm0 + mi * 16 + g;
            int c = n0 + wn0 + nj * 8 + tg * 2;
#pragma unroll
            for (int p = 0; p < 4; p++) {
                int rr = r + (p >> 1) * 8;
                int cc = c + (p & 1);
                float v = acc[mi][nj][p] * alpha;
                if (bias) v += bias[cc];
                if (RELU) v = fmaxf(v, 0.f);
                if (res) v += res[(size_t)rr * ldc + cc];
                C[(size_t)rr * ldc + cc] = v;
            }
        }
    }
}

// ---------------- launch ----------------
extern "C" void kernel_launch(void* const* d_in, const int* in_sizes, int n_in,
                              void* d_out, int out_size) {
    (void)in_sizes; (void)n_in; (void)out_size;

    const float* x     = (const float*)d_in[0];
    const float* g1    = (const float*)d_in[1];
    const float* beta1 = (const float*)d_in[2];
    const float* W_in  = (const float*)d_in[3];
    const float* b_in  = (const float*)d_in[4];
    const float* Wq    = (const float*)d_in[5];
    const float* bq    = (const float*)d_in[6];
    const float* Wk    = (const float*)d_in[7];
    const float* bk    = (const float*)d_in[8];
    const float* Wv    = (const float*)d_in[9];
    const float* bv    = (const float*)d_in[10];
    const float* Wo    = (const float*)d_in[11];
    const float* bo    = (const float*)d_in[12];
    const float* W2    = (const float*)d_in[13];
    const float* b2    = (const float*)d_in[14];
    const float* g2    = (const float*)d_in[15];
    const float* beta2 = (const float*)d_in[16];
    const float* Wf1   = (const float*)d_in[17];
    const float* bf1   = (const float*)d_in[18];
    const float* Wf2   = (const float*)d_in[19];
    const float* bf2   = (const float*)d_in[20];

    float* out  = (float*)d_out;
    float* attn = out + (size_t)SEQ * DM;   // [NH, SEQ, SEQ]

    float *normx, *h, *qkv, *wqkv, *bqkv, *ctx, *mha, *part1, *norm2, *ff1;
    cudaGetSymbolAddress((void**)&normx, g_normx);
    cudaGetSymbolAddress((void**)&h,     g_h);
    cudaGetSymbolAddress((void**)&qkv,   g_qkv);
    cudaGetSymbolAddress((void**)&wqkv,  g_wqkv);
    cudaGetSymbolAddress((void**)&bqkv,  g_bqkv);
    cudaGetSymbolAddress((void**)&ctx,   g_ctx);
    cudaGetSymbolAddress((void**)&mha,   g_mha);
    cudaGetSymbolAddress((void**)&part1, g_part1);
    cudaGetSymbolAddress((void**)&norm2, g_norm2);
    cudaGetSymbolAddress((void**)&ff1,   g_ff1);

    const long long SS = (long long)SEQ * SEQ;
    const int D3 = 3 * DM;

    // 0. pack fused QKV weights/bias (kernel, not memcpy nodes)
    pack_qkv_kernel<<<(DM * DM / 4) / 256, 256>>>(Wq, Wk, Wv, bq, bk, bv, wqkv, bqkv);

    // 1. LN1
    ln_kernel<<<SEQ, 256>>>(x, g1, beta1, normx);

    // 2. h = norm_x @ W_in + b_in
    mma_gemm<128, 128, 64, 32, false, false><<<dim3(DM / 128, SEQ / 128, 1), 256>>>(
        normx, W_in, b_in, nullptr, h, DM, DM, DM, DM, 0, 0, 0, 1.f);

    // 3. qkv = h @ W_qkv + b_qkv (fused)
    mma_gemm<128, 128, 64, 32, false, false><<<dim3(D3 / 128, SEQ / 128, 1), 256>>>(
        h, wqkv, bqkv, nullptr, qkv, DM, DM, D3, D3, 0, 0, 0, 1.f);

    // 4. scores = q @ k^T / 8 (per head)
    mma_gemm<128, 128, 64, 32, true, false><<<dim3(SEQ / 128, SEQ / 128, NH), 256>>>(
        qkv, qkv + DM, nullptr, nullptr, attn, DKH, D3, D3, SEQ,
        DKH, DKH, SS, 0.125f);

    // 5. causal softmax
    softmax_causal_kernel<<<dim3(SEQ, NH), 256>>>(attn);

    // 6. ctx = attn @ v (per head, N=64 tiles)
    mma_gemm<128, 64, 32, 32, false, false><<<dim3(1, SEQ / 128, NH), 256>>>(
        attn, qkv + 2 * DM, nullptr, nullptr, ctx, SEQ, SEQ, D3, DM,
        SS, DKH, DKH, 1.f);

    // 7. mha = ctx @ Wo + bo
    mma_gemm<128, 128, 64, 32, false, false><<<dim3(DM / 128, SEQ / 128, 1), 256>>>(
        ctx, Wo, bo, nullptr, mha, DM, DM, DM, DM, 0, 0, 0, 1.f);

    // 8. part1 = x + mha @ W2 + b2
    mma_gemm<128, 128, 64, 32, false, false><<<dim3(DM / 128, SEQ / 128, 1), 256>>>(
        mha, W2, b2, x, part1, DM, DM, DM, DM, 0, 0, 0, 1.f);

    // 9. LN2
    ln_kernel<<<SEQ, 256>>>(part1, g2, beta2, norm2);

    // 10. ff1 = relu(norm2 @ Wf1 + bf1)
    mma_gemm<128, 128, 64, 32, false, true><<<dim3(DFF / 128, SEQ / 128, 1), 256>>>(
        norm2, Wf1, bf1, nullptr, ff1, DM, DM, DFF, DFF, 0, 0, 0, 1.f);

    // 11. out = norm2 + ff1 @ Wf2 + bf2
    mma_gemm<128, 128, 64, 32, false, false><<<dim3(DM / 128, SEQ / 128, 1), 256>>>(
        ff1, Wf2, bf2, norm2, out, DFF, DFF, DM, DM, 0, 0, 0, 1.f);
}

// round 6
// speedup vs baseline: 1.7866x; 1.1115x over previous
#include <cuda_runtime.h>
#include <math.h>
#include <stdint.h>

#define SEQ 2048
#define DM  1024
#define DFF 4096
#define NH  16
#define DKH 64

// ---------------- scratch (no runtime allocation allowed) ----------------
__device__ float g_normx[SEQ * DM];
__device__ float g_h[SEQ * DM];
__device__ float g_qkv[SEQ * 3 * DM];
__device__ float g_wqkv[DM * 3 * DM];
__device__ float g_bqkv[3 * DM];
__device__ float g_ctx[SEQ * DM];
__device__ float g_mha[SEQ * DM];
__device__ float g_part1[SEQ * DM];
__device__ float g_norm2[SEQ * DM];
__device__ float g_ff1[SEQ * DFF];

// ---------------- helpers ----------------
__device__ __forceinline__ uint32_t f2tf32(float f) {
    uint32_t u;
    asm("cvt.rna.tf32.f32 %0, %1;" : "=r"(u) : "f"(f));
    return u;
}

__device__ __forceinline__ void mma_tf32(float* d, const uint32_t* a, const uint32_t* b) {
    asm volatile(
        "mma.sync.aligned.m16n8k8.row.col.f32.tf32.tf32.f32 "
        "{%0,%1,%2,%3}, {%4,%5,%6,%7}, {%8,%9}, {%0,%1,%2,%3};\n"
        : "+f"(d[0]), "+f"(d[1]), "+f"(d[2]), "+f"(d[3])
        : "r"(a[0]), "r"(a[1]), "r"(a[2]), "r"(a[3]), "r"(b[0]), "r"(b[1]));
}

// ---------------- pack W_qkv / b_qkv ----------------
__global__ void pack_qkv_kernel(const float* __restrict__ Wq,
                                const float* __restrict__ Wk,
                                const float* __restrict__ Wv,
                                const float* __restrict__ bq,
                                const float* __restrict__ bk,
                                const float* __restrict__ bv,
                                float* __restrict__ W, float* __restrict__ b) {
    int idx4 = blockIdx.x * 256 + threadIdx.x;      // over DM*DM/4 float4s
    int r  = idx4 / (DM / 4);
    int c4 = idx4 % (DM / 4);
    float4 q4 = *(const float4*)(Wq + (size_t)r * DM + c4 * 4);
    float4 k4 = *(const float4*)(Wk + (size_t)r * DM + c4 * 4);
    float4 v4 = *(const float4*)(Wv + (size_t)r * DM + c4 * 4);
    float* wr = W + (size_t)r * (3 * DM);
    *(float4*)(wr + c4 * 4)          = q4;
    *(float4*)(wr + DM + c4 * 4)     = k4;
    *(float4*)(wr + 2 * DM + c4 * 4) = v4;
    if (idx4 < DM) {
        b[idx4]          = bq[idx4];
        b[DM + idx4]     = bk[idx4];
        b[2 * DM + idx4] = bv[idx4];
    }
}

// ---------------- LayerNorm: y = g*((x-mean)/(std+eps)) + b ----------------
__global__ void ln_kernel(const float* __restrict__ x,
                          const float* __restrict__ gamma,
                          const float* __restrict__ beta,
                          float* __restrict__ out) {
    int row = blockIdx.x;
    const float* xr = x + (size_t)row * DM;
    __shared__ float red[256];
    int t = threadIdx.x;

    float s = 0.f;
    for (int i = t; i < DM; i += 256) s += xr[i];
    red[t] = s; __syncthreads();
    for (int off = 128; off > 0; off >>= 1) {
        if (t < off) red[t] += red[t + off];
        __syncthreads();
    }
    float mean = red[0] * (1.0f / DM);
    __syncthreads();

    float v = 0.f;
    for (int i = t; i < DM; i += 256) { float d = xr[i] - mean; v += d * d; }
    red[t] = v; __syncthreads();
    for (int off = 128; off > 0; off >>= 1) {
        if (t < off) red[t] += red[t + off];
        __syncthreads();
    }
    float rstd = 1.0f / (sqrtf(red[0] * (1.0f / DM)) + 1e-6f);

    float* o = out + (size_t)row * DM;
    for (int i = t; i < DM; i += 256)
        o[i] = gamma[i] * ((xr[i] - mean) * rstd) + beta[i];
}

// ---------------- causal softmax; zero masked tail ----------------
__global__ void softmax_causal_kernel(float* __restrict__ attn) {
    int row = blockIdx.x;
    int hh  = blockIdx.y;
    float* p = attn + ((size_t)hh * SEQ + row) * SEQ;
    int L = row + 1;
    int t = threadIdx.x;
    __shared__ float red[256];

    float m = -1e30f;
    for (int i = t; i < L; i += 256) m = fmaxf(m, p[i]);
    red[t] = m; __syncthreads();
    for (int off = 128; off > 0; off >>= 1) {
        if (t < off) red[t] = fmaxf(red[t], red[t + off]);
        __syncthreads();
    }
    m = red[0]; __syncthreads();

    float sum = 0.f;
    for (int i = t; i < L; i += 256) { float e = expf(p[i] - m); p[i] = e; sum += e; }
    red[t] = sum; __syncthreads();
    for (int off = 128; off > 0; off >>= 1) {
        if (t < off) red[t] += red[t + off];
        __syncthreads();
    }
    float inv = 1.0f / red[0];
    for (int i = t; i < L; i += 256) p[i] *= inv;
    for (int i = L + t; i < SEQ; i += 256) p[i] = 0.f;
}

// ---------------- 3xTF32 tensor-core GEMM (fragment-layout A, static smem) ----------------
// C[z] = alpha * A[z] (@ or @T) B[z] + bias (+relu) (+res)
// BM=128, 256 threads (8 warps), BK=16. Single smem buffer + register prefetch.
// A smem: per-fragment layout [s][frag][lane][4] -> one LDS.128 per mma fragment.
// B smem: classic [k][BN+8] (conflict-free).
template <int BM, int BN, int WM, int WN, bool NT, bool RELU>
__global__ void __launch_bounds__(256, 1)
mma_gemm(const float* __restrict__ A, const float* __restrict__ B,
         const float* __restrict__ bias, const float* __restrict__ res,
         float* __restrict__ C,
         int K, int lda, int ldb, int ldc,
         long long aZ, long long bZ, long long cZ, float alpha) {
    constexpr int BK = 16;
    static_assert(BM == 128, "BM must be 128");
    constexpr int BSTR = BN + 8;
    constexpr int WARPS_N = BN / WN;
    constexpr int MI = WM / 16;
    constexpr int NJ = WN / 8;
    static_assert((BM / WM) * (BN / WN) == 8, "8 warps");
    static_assert(!NT || BN == 128, "NT loader needs BN==128");
    constexpr int NB4 = (BK * BN) / (4 * 256);       // NN float4 loads / thread
    constexpr int ASEC = 2 * (BM / 16) * 128;        // 2048 words

    __shared__ __align__(16) uint32_t sAh[ASEC];
    __shared__ __align__(16) uint32_t sAl[ASEC];
    __shared__ __align__(16) uint32_t sBh[BK * BSTR];
    __shared__ __align__(16) uint32_t sBl[BK * BSTR];

    A += (size_t)blockIdx.z * aZ;
    B += (size_t)blockIdx.z * bZ;
    C += (size_t)blockIdx.z * cZ;

    const int tid  = threadIdx.x;
    const int lane = tid & 31;
    const int wid  = tid >> 5;
    const int g    = lane >> 2;   // 0..7
    const int tg   = lane & 3;    // 0..3

    const int m0 = blockIdx.y * BM;
    const int n0 = blockIdx.x * BN;
    const int wm0 = (wid / WARPS_N) * WM;
    const int wn0 = (wid % WARPS_N) * WN;

    float acc[MI][NJ][4];
#pragma unroll
    for (int i = 0; i < MI; i++)
#pragma unroll
        for (int j = 0; j < NJ; j++)
#pragma unroll
            for (int c = 0; c < 4; c++) acc[i][j][c] = 0.f;

    // register staging
    float raf[2][4];     // A: [s][reg], reg = h + 2q; warp owns fragment row-pair wid
    float rbN[NB4 ? NB4 : 1][4];
    float rbT[2][4];     // NT B: [jj][s*2+q]; warp owns nj = wid*2 + jj

    auto loadA = [&](int k0) {
        const float* Ab = A + (size_t)(m0 + wid * 16 + g) * lda + k0 + tg;
#pragma unroll
        for (int s = 0; s < 2; s++)
#pragma unroll
            for (int q = 0; q < 2; q++) {
                raf[s][0 + 2 * q] = Ab[s * 8 + 4 * q];                      // h=0
                raf[s][1 + 2 * q] = Ab[(size_t)8 * lda + s * 8 + 4 * q];    // h=1
            }
    };
    auto storeA = [&]() {
#pragma unroll
        for (int s = 0; s < 2; s++) {
            uint4 hi4, lo4;
            uint32_t* hp = (uint32_t*)&hi4;
            uint32_t* lp = (uint32_t*)&lo4;
#pragma unroll
            for (int r = 0; r < 4; r++) {
                hp[r] = f2tf32(raf[s][r]);
                lp[r] = f2tf32(raf[s][r] - __uint_as_float(hp[r]));
            }
            int off = (s * (BM / 16) + wid) * 128 + lane * 4;
            *(uint4*)&sAh[off] = hi4;
            *(uint4*)&sAl[off] = lo4;
        }
    };

    auto loadB = [&](int k0) {
        if (NT) {
#pragma unroll
            for (int jj = 0; jj < 2; jj++) {
                const float* Bb = B + (size_t)(n0 + (wid * 2 + jj) * 8 + g) * ldb + k0 + tg;
#pragma unroll
                for (int s = 0; s < 2; s++)
#pragma unroll
                    for (int q = 0; q < 2; q++)
                        rbT[jj][s * 2 + q] = Bb[s * 8 + 4 * q];
            }
        } else {
#pragma unroll
            for (int i = 0; i < NB4; i++) {
                int flat = tid + i * 256;
                int r = flat / (BN / 4), c4 = flat % (BN / 4);
                *(float4*)rbN[i] = *(const float4*)(B + (size_t)(k0 + r) * ldb + n0 + c4 * 4);
            }
        }
    };
    auto storeB = [&]() {
        if (NT) {
#pragma unroll
            for (int jj = 0; jj < 2; jj++)
#pragma unroll
                for (int s = 0; s < 2; s++)
#pragma unroll
                    for (int q = 0; q < 2; q++) {
                        float f = rbT[jj][s * 2 + q];
                        uint32_t hi = f2tf32(f);
                        uint32_t lo = f2tf32(f - __uint_as_float(hi));
                        int row = s * 8 + 4 * q + tg;
                        int col = (wid * 2 + jj) * 8 + g;
                        int off = row * BSTR + col;
                        sBh[off] = hi;
                        sBl[off] = lo;
                    }
        } else {
#pragma unroll
            for (int i = 0; i < NB4; i++) {
                int flat = tid + i * 256;
                int r = flat / (BN / 4), c4 = flat % (BN / 4);
                uint4 hi4, lo4;
                uint32_t* hp = (uint32_t*)&hi4;
                uint32_t* lp = (uint32_t*)&lo4;
#pragma unroll
                for (int j = 0; j < 4; j++) {
                    hp[j] = f2tf32(rbN[i][j]);
                    lp[j] = f2tf32(rbN[i][j] - __uint_as_float(hp[j]));
                }
                int off = r * BSTR + c4 * 4;
                *(uint4*)&sBh[off] = hi4;
                *(uint4*)&sBl[off] = lo4;
            }
        }
    };

    auto compute = [&]() {
#pragma unroll
        for (int kk = 0; kk < BK; kk += 8) {
            const int s = kk >> 3;
            uint4 ah[MI], al[MI];
#pragma unroll
            for (int mi = 0; mi < MI; mi++) {
                int off = (s * (BM / 16) + (wm0 / 16 + mi)) * 128 + lane * 4;
                ah[mi] = *(const uint4*)&sAh[off];
                al[mi] = *(const uint4*)&sAl[off];
            }
            uint32_t bh[NJ][2], bl[NJ][2];
#pragma unroll
            for (int nj = 0; nj < NJ; nj++) {
                int c  = wn0 + nj * 8 + g;
                int r0 = (kk + tg) * BSTR + c;
                int r1 = r0 + 4 * BSTR;
                bh[nj][0] = sBh[r0]; bh[nj][1] = sBh[r1];
                bl[nj][0] = sBl[r0]; bl[nj][1] = sBl[r1];
            }
#pragma unroll
            for (int mi = 0; mi < MI; mi++)
#pragma unroll
                for (int nj = 0; nj < NJ; nj++) {
                    mma_tf32(acc[mi][nj], (const uint32_t*)&al[mi], bh[nj]);
                    mma_tf32(acc[mi][nj], (const uint32_t*)&ah[mi], bl[nj]);
                    mma_tf32(acc[mi][nj], (const uint32_t*)&ah[mi], bh[nj]);
                }
        }
    };

    // prologue
    loadA(0); loadB(0);
    storeA(); storeB();
    __syncthreads();

    const int nIt = K / BK;
    for (int it = 0; it < nIt; it++) {
        if (it + 1 < nIt) { loadA((it + 1) * BK); loadB((it + 1) * BK); }
        compute();
        if (it + 1 < nIt) {
            __syncthreads();
            storeA(); storeB();
            __syncthreads();
        }
    }

    // epilogue
#pragma unroll
    for (int mi = 0; mi < MI; mi++) {
#pragma unroll
        for (int nj = 0; nj < NJ; nj++) {
            int r = m0 + wm0 + mi * 16 + g;
            int c = n0 + wn0 + nj * 8 + tg * 2;
#pragma unroll
            for (int p = 0; p < 4; p++) {
                int rr = r + (p >> 1) * 8;
                int cc = c + (p & 1);
                float v = acc[mi][nj][p] * alpha;
                if (bias) v += bias[cc];
                if (RELU) v = fmaxf(v, 0.f);
                if (res) v += res[(size_t)rr * ldc + cc];
                C[(size_t)rr * ldc + cc] = v;
            }
        }
    }
}

// ---------------- launch ----------------
extern "C" void kernel_launch(void* const* d_in, const int* in_sizes, int n_in,
                              void* d_out, int out_size) {
    (void)in_sizes; (void)n_in; (void)out_size;

    const float* x     = (const float*)d_in[0];
    const float* g1    = (const float*)d_in[1];
    const float* beta1 = (const float*)d_in[2];
    const float* W_in  = (const float*)d_in[3];
    const float* b_in  = (const float*)d_in[4];
    const float* Wq    = (const float*)d_in[5];
    const float* bq    = (const float*)d_in[6];
    const float* Wk    = (const float*)d_in[7];
    const float* bk    = (const float*)d_in[8];
    const float* Wv    = (const float*)d_in[9];
    const float* bv    = (const float*)d_in[10];
    const float* Wo    = (const float*)d_in[11];
    const float* bo    = (const float*)d_in[12];
    const float* W2    = (const float*)d_in[13];
    const float* b2    = (const float*)d_in[14];
    const float* g2    = (const float*)d_in[15];
    const float* beta2 = (const float*)d_in[16];
    const float* Wf1   = (const float*)d_in[17];
    const float* bf1   = (const float*)d_in[18];
    const float* Wf2   = (const float*)d_in[19];
    const float* bf2   = (const float*)d_in[20];

    float* out  = (float*)d_out;
    float* attn = out + (size_t)SEQ * DM;   // [NH, SEQ, SEQ]

    float *normx, *h, *qkv, *wqkv, *bqkv, *ctx, *mha, *part1, *norm2, *ff1;
    cudaGetSymbolAddress((void**)&normx, g_normx);
    cudaGetSymbolAddress((void**)&h,     g_h);
    cudaGetSymbolAddress((void**)&qkv,   g_qkv);
    cudaGetSymbolAddress((void**)&wqkv,  g_wqkv);
    cudaGetSymbolAddress((void**)&bqkv,  g_bqkv);
    cudaGetSymbolAddress((void**)&ctx,   g_ctx);
    cudaGetSymbolAddress((void**)&mha,   g_mha);
    cudaGetSymbolAddress((void**)&part1, g_part1);
    cudaGetSymbolAddress((void**)&norm2, g_norm2);
    cudaGetSymbolAddress((void**)&ff1,   g_ff1);

    const long long SS = (long long)SEQ * SEQ;
    const int D3 = 3 * DM;

    // 0. pack fused QKV weights/bias
    pack_qkv_kernel<<<(DM * DM / 4) / 256, 256>>>(Wq, Wk, Wv, bq, bk, bv, wqkv, bqkv);

    // 1. LN1
    ln_kernel<<<SEQ, 256>>>(x, g1, beta1, normx);

    // 2. h = norm_x @ W_in + b_in
    mma_gemm<128, 128, 64, 32, false, false><<<dim3(DM / 128, SEQ / 128, 1), 256>>>(
        normx, W_in, b_in, nullptr, h, DM, DM, DM, DM, 0, 0, 0, 1.f);

    // 3. qkv = h @ W_qkv + b_qkv (fused)
    mma_gemm<128, 128, 64, 32, false, false><<<dim3(D3 / 128, SEQ / 128, 1), 256>>>(
        h, wqkv, bqkv, nullptr, qkv, DM, DM, D3, D3, 0, 0, 0, 1.f);

    // 4. scores = q @ k^T / 8 (per head)
    mma_gemm<128, 128, 64, 32, true, false><<<dim3(SEQ / 128, SEQ / 128, NH), 256>>>(
        qkv, qkv + DM, nullptr, nullptr, attn, DKH, D3, D3, SEQ,
        DKH, DKH, SS, 0.125f);

    // 5. causal softmax
    softmax_causal_kernel<<<dim3(SEQ, NH), 256>>>(attn);

    // 6. ctx = attn @ v (per head, N=64 tiles)
    mma_gemm<128, 64, 32, 32, false, false><<<dim3(1, SEQ / 128, NH), 256>>>(
        attn, qkv + 2 * DM, nullptr, nullptr, ctx, SEQ, SEQ, D3, DM,
        SS, DKH, DKH, 1.f);

    // 7. mha = ctx @ Wo + bo
    mma_gemm<128, 128, 64, 32, false, false><<<dim3(DM / 128, SEQ / 128, 1), 256>>>(
        ctx, Wo, bo, nullptr, mha, DM, DM, DM, DM, 0, 0, 0, 1.f);

    // 8. part1 = x + mha @ W2 + b2
    mma_gemm<128, 128, 64, 32, false, false><<<dim3(DM / 128, SEQ / 128, 1), 256>>>(
        mha, W2, b2, x, part1, DM, DM, DM, DM, 0, 0, 0, 1.f);

    // 9. LN2
    ln_kernel<<<SEQ, 256>>>(part1, g2, beta2, norm2);

    // 10. ff1 = relu(norm2 @ Wf1 + bf1)
    mma_gemm<128, 128, 64, 32, false, true><<<dim3(DFF / 128, SEQ / 128, 1), 256>>>(
        norm2, Wf1, bf1, nullptr, ff1, DM, DM, DFF, DFF, 0, 0, 0, 1.f);

    // 11. out = norm2 + ff1 @ Wf2 + bf2
    mma_gemm<128, 128, 64, 32, false, false><<<dim3(DM / 128, SEQ / 128, 1), 256>>>(
        ff1, Wf2, bf2, norm2, out, DFF, DFF, DM, DM, 0, 0, 0, 1.f);
}